// round 15
// baseline (speedup 1.0000x reference)
#include <cuda_runtime.h>
#include <cuda_fp16.h>
#include <math.h>
#include <stdint.h>

#define TS 8192
#define BB 64
#define LL 128
#define DLN 20
#define TP 272      // fp16 tile pitch in BYTES (136 halves)
#define SP 132      // fp32 stage pitch in floats

typedef unsigned long long ull;

// ---------------- scratch (device globals; no allocation allowed) ----------
__device__ float g_gi[TS * 768];                     // 25 MB
__device__ float g_pooled[BB * 256];
__device__ __align__(16) __half g_Af[TS * 128];      // stmt_h, fp16

// subtree sizes of the 32-node binary heap
__constant__ float c_cszf[32] = {32,16,15,8,7,7,7,4,3,3,3,3,3,3,3,2,
                                 1,1,1,1,1,1,1,1,1,1,1,1,1,1,1,1};

// ---------------- helpers ---------------------------------------------------
__device__ __forceinline__ uint32_t s2u(const void* p){
    uint32_t a;
    asm("{ .reg .u64 t; cvta.to.shared.u64 t, %1; cvt.u32.u64 %0, t; }" : "=r"(a) : "l"(p));
    return a;
}
__device__ __forceinline__ void ldsm4(uint32_t addr, uint32_t r[4]){
    asm volatile("ldmatrix.sync.aligned.m8n8.x4.shared.b16 {%0,%1,%2,%3}, [%4];"
        : "=r"(r[0]), "=r"(r[1]), "=r"(r[2]), "=r"(r[3]) : "r"(addr));
}
__device__ __forceinline__ void mma_f16(float d[4], const uint32_t a[4], uint32_t b0, uint32_t b1){
    asm volatile("mma.sync.aligned.m16n8k16.row.col.f32.f16.f16.f32 "
        "{%0,%1,%2,%3}, {%4,%5,%6,%7}, {%8,%9}, {%0,%1,%2,%3};"
        : "+f"(d[0]), "+f"(d[1]), "+f"(d[2]), "+f"(d[3])
        : "r"(a[0]), "r"(a[1]), "r"(a[2]), "r"(a[3]), "r"(b0), "r"(b1));
}
__device__ __forceinline__ float4 f4add(float4 a, float4 b){
    return make_float4(a.x + b.x, a.y + b.y, a.z + b.z, a.w + b.w);
}
__device__ __forceinline__ void cpa16(uint32_t dst, const void* src){
    asm volatile("cp.async.cg.shared.global [%0], [%1], 16;"
        :: "r"(dst), "l"(__cvta_generic_to_global(src)) : "memory");
}
#define CP_COMMIT() asm volatile("cp.async.commit_group;" ::: "memory")
#define CP_WAIT0()  asm volatile("cp.async.wait_group 0;" ::: "memory")

// smem layouts (byte offsets from aligned base). One 128x136 fp16 tile = 34816 B.
// K1:  A | B | stage
#define K1_OFF_A   0
#define K1_OFF_B   34816
#define K1_OFF_STG 69632                 // float[128][132] = 67584 B
#define K1_DYN  (1024 + 69632 + 67584)
// K1b: B | A0 | A1
#define K1B_OFF_B  0
#define K1B_OFF_A0 34816
#define K1B_OFF_A1 69632
#define K1B_DYN (1024 + 104448)
// K2: Wb staged in dynamic smem (attention CTAs only)
#define K2_DYN (128 * 128 * 4)

// 128x64x128 fp16 1-term GEMM slice: warp (wr, wc) does rows 16*wr..+15,
// cols 64*wc..+63 (8 n-tiles).
__device__ __forceinline__ void gemm_tile8_1t(
    uint32_t sA, uint32_t sB,
    int wr, int wc, int lane, float acc[8][4])
{
    const uint32_t aOff = (uint32_t)(((lane & 15) + 16 * wr) * TP + ((lane >> 4) << 4));
    const uint32_t bOff = (uint32_t)((64 * wc + ((lane >> 4) << 3) + (lane & 7)) * TP
                                     + (((lane >> 3) & 1) << 4));
    #pragma unroll
    for (int ks = 0; ks < 8; ks++) {
        const uint32_t ko = ks * 32;          // 16 halves = 32 B
        uint32_t a[4];
        ldsm4(sA + aOff + ko, a);
        uint32_t bP = sB + bOff + ko;
        #pragma unroll
        for (int p = 0; p < 4; p++) {
            uint32_t bh[4];
            ldsm4(bP, bh);
            mma_f16(acc[2 * p],     a, bh[0], bh[1]);
            mma_f16(acc[2 * p + 1], a, bh[2], bh[3]);
            bP += 16 * TP;
        }
    }
}

// convert a 128x128 fp32 weight block (row-major, gmem) into fp16 smem tile
__device__ __forceinline__ void conv_w_tile(char* dst, const float* __restrict__ src, int t){
    #pragma unroll
    for (int i = 0; i < 8; i++) {
        int idx = i * 512 + t;
        int j = idx >> 5, c4 = idx & 31;
        float4 v = *(const float4*)(src + j * 128 + c4 * 4);
        __half2 h0, h1;
        h0.x = __float2half_rn(v.x); h0.y = __float2half_rn(v.y);
        h1.x = __float2half_rn(v.z); h1.y = __float2half_rn(v.w);
        *(__half2*)(dst + j * TP + c4 * 8)     = h0;
        *(__half2*)(dst + j * TP + c4 * 8 + 4) = h1;
    }
}

// issue cp.async gather of 128 embedding rows (512B each) into stage
__device__ __forceinline__ void gather_pref(
    uint32_t stg_u, const float* __restrict__ emb, const int* tk_s, int t)
{
    #pragma unroll
    for (int i = 0; i < 8; i++) {
        int idx = i * 512 + t;
        int row = idx >> 5, ch = idx & 31;
        cpa16(stg_u + (uint32_t)(row * (SP * 4) + ch * 16),
              emb + (size_t)tk_s[row] * 128 + ch * 4);
    }
    CP_COMMIT();
}

// ---------------------------------------------------------------------------
// K1: persistent (grid 148, 512 thr). Per tile (4 statements): prefetched
//     gather -> tree reduce (2 barriers) -> fp16 round -> 1-term mma.sync
//     GEMM vs Wc -> shuffle epilogue -> fp16 staging.
// ---------------------------------------------------------------------------
__global__ __launch_bounds__(512) void k1_stmt(
    const float* __restrict__ emb, const float* __restrict__ Wc,
    const float* __restrict__ bc, const int* __restrict__ toks_g)
{
    extern __shared__ char smraw[];
    __shared__ int tkA[128], tkB[128];
    __shared__ float bcs[128];
    __shared__ float epi[1024];

    const int t = threadIdx.x, w = t >> 5, lane = t & 31;
    const int wr = w & 7, wc = w >> 3;
    const uint32_t rawu = s2u(smraw);
    const uint32_t alu = (rawu + 1023u) & ~1023u;
    char* base = smraw + (alu - rawu);
    float* stg = (float*)(base + K1_OFF_STG);
    float4* As4 = (float4*)stg;
    const uint32_t stg_u = alu + K1_OFF_STG;

    if (t < 128) { bcs[t] = bc[t]; tkA[t] = toks_g[blockIdx.x * 128 + t] + 1; }
    __syncthreads();
    gather_pref(stg_u, emb, tkA, t);
    if ((int)blockIdx.x + 148 < 2048 && t < 128)
        tkB[t] = toks_g[(blockIdx.x + 148) * 128 + t] + 1;

    // Wc fp16 tile once (converted in-CTA from gmem)
    conv_w_tile(base + K1_OFF_B, Wc, t);

    int jpar = 0;
    for (int tile = blockIdx.x; tile < 2048; tile += 148, jpar ^= 1) {
        CP_WAIT0();
        __syncthreads();

        // ---- tree reduce. Pass A: L4 fused into p=7 task + L3 (p=7..14) ----
        #pragma unroll
        for (int i = 0; i < 2; i++) {
            int idx = i * 512 + t;
            int k4 = idx & 31, q = idx >> 5, tt = q & 3, p = 7 + (q >> 2);
            int rb = tt * 32;
            if (p == 7) {
                float4 a15 = f4add(As4[(rb + 15) * 33 + k4], As4[(rb + 31) * 33 + k4]);
                As4[(rb + 15) * 33 + k4] = a15;
                As4[(rb + 7) * 33 + k4] = f4add(As4[(rb + 7) * 33 + k4],
                                          f4add(a15, As4[(rb + 16) * 33 + k4]));
            } else {
                As4[(rb + p) * 33 + k4] = f4add(As4[(rb + p) * 33 + k4],
                    f4add(As4[(rb + 2 * p + 1) * 33 + k4], As4[(rb + 2 * p + 2) * 33 + k4]));
            }
        }
        __syncthreads();
        // ---- Pass B: L2+L1+L0 fused per (stmt, k4) column, register chain ----
        if (t < 128) {
            int tt = t >> 5, k4 = t & 31;
            int rb = tt * 32;
            #define AV(p) As4[(rb + (p)) * 33 + k4]
            float4 a3 = f4add(AV(3), f4add(AV(7),  AV(8)));  AV(3) = a3;
            float4 a4 = f4add(AV(4), f4add(AV(9),  AV(10))); AV(4) = a4;
            float4 a5 = f4add(AV(5), f4add(AV(11), AV(12))); AV(5) = a5;
            float4 a6 = f4add(AV(6), f4add(AV(13), AV(14))); AV(6) = a6;
            float4 a1 = f4add(AV(1), f4add(a3, a4)); AV(1) = a1;
            float4 a2 = f4add(AV(2), f4add(a5, a6)); AV(2) = a2;
            AV(0) = f4add(AV(0), f4add(a1, a2));
            #undef AV
        }
        __syncthreads();

        // ---- fp32 -> fp16 A tile (single rounding) ----
        #pragma unroll
        for (int i = 0; i < 16; i++) {
            int idx = i * 512 + t;
            int row = idx >> 6, c2 = idx & 63;
            float2 v = *(const float2*)(stg + row * SP + c2 * 2);
            __half2 hh;
            hh.x = __float2half_rn(v.x);
            hh.y = __float2half_rn(v.y);
            *(__half2*)(base + K1_OFF_A + row * TP + c2 * 4) = hh;
        }
        __syncthreads();

        // ---- prefetch next tile's gather into (now free) stage ----
        int nxt = tile + 148;
        if (nxt < 2048) gather_pref(stg_u, emb, jpar ? tkA : tkB, t);
        if (nxt + 148 < 2048 && t < 128)
            (jpar ? tkB : tkA)[t] = toks_g[(nxt + 148) * 128 + t] + 1;

        // ---- GEMM (16 warps: wr x wc), 1-term fp16 ----
        float acc[8][4];
        #pragma unroll
        for (int n = 0; n < 8; n++)
            #pragma unroll
            for (int c = 0; c < 4; c++) acc[n][c] = 0.f;
        gemm_tile8_1t(alu + K1_OFF_A, alu + K1_OFF_B, wr, wc, lane, acc);

        // ---- shuffle epilogue: max over 32 nodes of acc + csz*bc, relu ----
        const int rr0 = (wr & 1) * 16 + (lane >> 2);
        const float cz0 = c_cszf[rr0], cz1 = c_cszf[rr0 + 8];
        #pragma unroll
        for (int nt = 0; nt < 8; nt++) {
            int c0 = 64 * wc + nt * 8 + 2 * (lane & 3);
            float b0 = bcs[c0], b1 = bcs[c0 + 1];
            float m0 = fmaxf(acc[nt][0] + cz0 * b0, acc[nt][2] + cz1 * b0);
            float m1 = fmaxf(acc[nt][1] + cz0 * b1, acc[nt][3] + cz1 * b1);
            #pragma unroll
            for (int o = 4; o <= 16; o <<= 1) {
                m0 = fmaxf(m0, __shfl_xor_sync(0xffffffffu, m0, o));
                m1 = fmaxf(m1, __shfl_xor_sync(0xffffffffu, m1, o));
            }
            if ((lane >> 2) == 0) { epi[wr * 128 + c0] = m0; epi[wr * 128 + c0 + 1] = m1; }
        }
        __syncthreads();
        {
            int st = t >> 7, col = t & 127;
            float m = fmaxf(fmaxf(epi[(2 * st) * 128 + col], epi[(2 * st + 1) * 128 + col]), 0.f);
            g_Af[(tile * 4 + st) * 128 + col] = __float2half_rn(m);
        }
        __syncthreads();
    }
}

// ---------------------------------------------------------------------------
// K1b: persistent gi GEMM (512 thr). 144 CTAs = (24 rb-groups x 6 gate-blocks).
//      B converted once from gmem; fp16 A double-buffered via cp.async.
//      Adds bih bias (pre-folded out of k2).
// ---------------------------------------------------------------------------
__device__ __forceinline__ void k1b_prefA(uint32_t dstA, int rb, int t){
    const float4* sa = (const float4*)(g_Af + rb * 16384);
    #pragma unroll
    for (int i = 0; i < 4; i++) {
        int idx = i * 512 + t, jj = idx >> 4, sg = idx & 15;
        cpa16(dstA + jj * TP + sg * 16, sa + idx);
    }
    CP_COMMIT();
}

__global__ __launch_bounds__(512) void k1b_gi(
    const float* __restrict__ Wih_f, const float* __restrict__ Wih_b,
    const float* __restrict__ bih_f, const float* __restrict__ bih_b)
{
    extern __shared__ char smraw[];
    __shared__ float bias_s[128];
    const int t = threadIdx.x, w = t >> 5, lane = t & 31;
    const int wr = w & 7, wc = w >> 3;
    const int by = blockIdx.x % 6, rb0 = blockIdx.x / 6;
    const uint32_t rawu = s2u(smraw);
    const uint32_t alu = (rawu + 1023u) & ~1023u;
    char* base = smraw + (alu - rawu);

    if (t < 128) bias_s[t] = (by < 3) ? bih_f[by * 128 + t] : bih_b[(by - 3) * 128 + t];

    k1b_prefA(alu + K1B_OFF_A0, rb0, t);

    // B gate-block once (converted in-CTA from gmem)
    {
        const float* Wsel = (by < 3) ? (Wih_f + (size_t)by * 128 * 128)
                                     : (Wih_b + (size_t)(by - 3) * 128 * 128);
        conv_w_tile(base + K1B_OFF_B, Wsel, t);
    }

    int pb = 0;
    for (int rb = rb0; rb < 64; rb += 24, pb ^= 1) {
        CP_WAIT0();
        __syncthreads();
        if (rb + 24 < 64)
            k1b_prefA(alu + (pb ? K1B_OFF_A0 : K1B_OFF_A1), rb + 24, t);

        float acc[8][4];
        #pragma unroll
        for (int n = 0; n < 8; n++)
            #pragma unroll
            for (int c = 0; c < 4; c++) acc[n][c] = 0.f;
        gemm_tile8_1t(alu + (pb ? K1B_OFF_A1 : K1B_OFF_A0),
                      alu + K1B_OFF_B, wr, wc, lane, acc);

        const int row = rb * 128 + 16 * wr + (lane >> 2);
        float* o0 = g_gi + (size_t)row * 768 + by * 128 + 64 * wc;
        float* o1 = o0 + 8 * 768;
        const int cb = (lane & 3) * 2;
        #pragma unroll
        for (int nt = 0; nt < 8; nt++) {
            float b0 = bias_s[64 * wc + nt * 8 + cb];
            float b1 = bias_s[64 * wc + nt * 8 + cb + 1];
            *(float2*)(o0 + nt * 8 + cb) = make_float2(acc[nt][0] + b0, acc[nt][1] + b1);
            *(float2*)(o1 + nt * 8 + cb) = make_float2(acc[nt][2] + b0, acc[nt][3] + b1);
        }
    }
}

// ---------------------------------------------------------------------------
__device__ __forceinline__ void ffma2(ull& d, ull a, ull b){
    asm("fma.rn.f32x2 %0, %1, %2, %0;" : "+l"(d) : "l"(a), "l"(b));
}
__device__ __forceinline__ float2 ull2f2(ull v){
    float2 f; asm("mov.b64 {%0, %1}, %2;" : "=f"(f.x), "=f"(f.y) : "l"(v)); return f;
}

// ---------------------------------------------------------------------------
// K2 (fused): CTAs 0..127 = GRU recurrence (one per batch,dir); CTAs 128..143
//     = doc-attention rvec (4 batches each) hidden under the recurrence.
// ---------------------------------------------------------------------------
__global__ __launch_bounds__(384) void k2_gru(
    const float* __restrict__ Whh_f, const float* __restrict__ bhh_f,
    const float* __restrict__ Whh_b, const float* __restrict__ bhh_b,
    const float* __restrict__ emb, const float* __restrict__ Wb,
    const int* __restrict__ doc, float* __restrict__ out)
{
    extern __shared__ float Wbs[];           // 64 KB (attention CTAs only)
    __shared__ float h_s[128];
    __shared__ float part[768];              // [half][row]
    __shared__ float demb[DLN * 128];
    __shared__ float u_s[128];
    __shared__ float exs[32];
    __shared__ float inv_s;
    __shared__ int dti[DLN];

    const int t = threadIdx.x, wid = t >> 5, lane = t & 31;

    if (blockIdx.x >= 128) {
        // ================= rvec attention: 4 batches per CTA ================
        const int b0 = (blockIdx.x - 128) * 4;
        // stage Wb once (4096 float4 over 384 threads)
        #pragma unroll
        for (int i = 0; i < 11; i++) {
            int idx = i * 384 + t;
            if (idx < 4096) *(float4*)(Wbs + idx * 4) = *(const float4*)(Wb + idx * 4);
        }
        for (int b = b0; b < b0 + 4; b++) {
            if (t < DLN) dti[t] = doc[b * DLN + t] + 1;
            __syncthreads();
            #pragma unroll
            for (int i = 0; i < 2; i++) {
                int idx = i * 384 + t;
                if (idx < DLN * 32) {
                    int l = idx >> 5, c4 = idx & 31;
                    *(float4*)(demb + l * 128 + c4 * 4) =
                        *(const float4*)(emb + (size_t)dti[l] * 128 + c4 * 4);
                }
            }
            __syncthreads();
            if (t < 128) {
                float s = 0.f;
                #pragma unroll
                for (int l = 0; l < DLN; l++) s += demb[l * 128 + t];
                part[t] = s * (1.f / (float)DLN);   // h0 in part[0:128]
            }
            __syncthreads();
            // u = Wb @ h0 from smem
            for (int row = wid; row < 128; row += 12) {
                const float* wr = Wbs + row * 128;
                float s = wr[lane] * part[lane] + wr[lane + 32] * part[lane + 32]
                        + wr[lane + 64] * part[lane + 64] + wr[lane + 96] * part[lane + 96];
                #pragma unroll
                for (int o = 16; o > 0; o >>= 1) s += __shfl_xor_sync(0xffffffffu, s, o);
                if (lane == 0) u_s[row] = s;
            }
            __syncthreads();
            for (int l = wid; l < DLN; l += 12) {
                const float* dr = demb + l * 128;
                float s = dr[lane] * u_s[lane] + dr[lane + 32] * u_s[lane + 32]
                        + dr[lane + 64] * u_s[lane + 64] + dr[lane + 96] * u_s[lane + 96];
                #pragma unroll
                for (int o = 16; o > 0; o >>= 1) s += __shfl_xor_sync(0xffffffffu, s, o);
                if (lane == 0) exs[l] = s;
            }
            __syncthreads();
            if (wid == 0) {
                float v = (lane < DLN) ? exs[lane] : -3e38f;
                float m = v;
                #pragma unroll
                for (int o = 16; o > 0; o >>= 1) m = fmaxf(m, __shfl_xor_sync(0xffffffffu, m, o));
                float e = (lane < DLN) ? expf(v - m) : 0.f;
                float ssum = e;
                #pragma unroll
                for (int o = 16; o > 0; o >>= 1) ssum += __shfl_xor_sync(0xffffffffu, ssum, o);
                if (lane < DLN) exs[lane] = e;
                if (lane == 0) inv_s = 1.f / ssum;
            }
            __syncthreads();
            if (t < 128) {
                float rv = 0.f;
                #pragma unroll
                for (int l = 0; l < DLN; l++) rv += exs[l] * demb[l * 128 + t];
                out[BB * 128 + b * 128 + t] = rv * inv_s;
            }
            __syncthreads();
        }
        return;
    }

    // ======================= GRU recurrence =============================
    const int b = blockIdx.x >> 1, dir = blockIdx.x & 1;
    const float* Whh = dir ? Whh_b : Whh_f;
    const float* bhh = dir ? bhh_b : bhh_f;

    const int g  = (t < 192) ? 0 : 1;
    const int tt = (t < 192) ? t : t - 192;
    const int j0 = 2 * tt;                   // rows j0, j0+1

    ull w0[32], w1[32];                      // 2 rows x 64 cols fp32
    {
        const ulonglong2* p0 = (const ulonglong2*)(Whh + (size_t)j0 * 128 + g * 64);
        const ulonglong2* p1 = (const ulonglong2*)(Whh + (size_t)(j0 + 1) * 128 + g * 64);
        #pragma unroll
        for (int i = 0; i < 16; i++) {
            ulonglong2 v0 = p0[i]; w0[2*i] = v0.x; w0[2*i+1] = v0.y;
            ulonglong2 v1 = p1[i]; w1[2*i] = v1.x; w1[2*i+1] = v1.y;
        }
    }
    float bhr = 0.f, bhz = 0.f, bhn = 0.f;
    if (t < 128) {
        bhr = bhh[t]; bhz = bhh[128 + t]; bhn = bhh[256 + t];
        h_s[t] = 0.f;
    }

    const float* gbase = g_gi + (size_t)(b * LL + (dir ? LL - 1 : 0)) * 768 + dir * 384;
    const int stp = dir ? -768 : 768;
    __syncthreads();

    float hmax = -3e38f;
    for (int l = 0; l < LL; l++) {
        float gr, gz, gn;
        if (t < 128) {
            const float* gp = gbase + (ptrdiff_t)l * stp;
            gr = __ldg(gp + t);
            gz = __ldg(gp + 128 + t);
            gn = __ldg(gp + 256 + t);
        }

        ull a00 = 0, a01 = 0, a10 = 0, a11 = 0;
        const ulonglong2* hp = (const ulonglong2*)(h_s + g * 64);
        #pragma unroll
        for (int i = 0; i < 16; i++) {
            ulonglong2 hv = hp[i];
            ffma2(a00, w0[2*i],     hv.x);
            ffma2(a01, w0[2*i + 1], hv.y);
            ffma2(a10, w1[2*i],     hv.x);
            ffma2(a11, w1[2*i + 1], hv.y);
        }
        float2 f00 = ull2f2(a00), f01 = ull2f2(a01);
        float2 f10 = ull2f2(a10), f11 = ull2f2(a11);
        *(float2*)(part + g * 384 + j0) = make_float2(
            (f00.x + f00.y) + (f01.x + f01.y),
            (f10.x + f10.y) + (f11.x + f11.y));
        __syncthreads();

        if (t < 128) {
            float ghr = part[t]       + part[384 + t] + bhr;
            float ghz = part[128 + t] + part[512 + t] + bhz;
            float ghn = part[256 + t] + part[640 + t] + bhn;
            float r = __fdividef(1.f, 1.f + __expf(-(gr + ghr)));
            float z = __fdividef(1.f, 1.f + __expf(-(gz + ghz)));
            float y = gn + r * ghn;
            float n = 1.f - __fdividef(2.f, __expf(2.f * y) + 1.f);
            float hnew = (1.f - z) * n + z * h_s[t];
            h_s[t] = hnew;
            hmax = fmaxf(hmax, hnew);
        }
        __syncthreads();
    }
    if (t < 128) g_pooled[b * 256 + dir * 128 + t] = hmax;
}

// ---------------------------------------------------------------------------
// K3: lvec only = pooled @ linW^T + linb. One CTA per batch.
// ---------------------------------------------------------------------------
__global__ __launch_bounds__(256) void k3_out(
    const float* __restrict__ linW, const float* __restrict__ linb,
    float* __restrict__ out)
{
    __shared__ float pool[256];
    const int t = threadIdx.x, b = blockIdx.x;
    const int wid = t >> 5, lane = t & 31;

    pool[t] = g_pooled[b * 256 + t];
    __syncthreads();
    #pragma unroll
    for (int rr = 0; rr < 16; rr++) {
        int row = wid * 16 + rr;
        const float* wr = linW + row * 256;
        float s = 0.f;
        #pragma unroll
        for (int q = 0; q < 8; q++) s += wr[lane + 32 * q] * pool[lane + 32 * q];
        #pragma unroll
        for (int o = 16; o > 0; o >>= 1) s += __shfl_xor_sync(0xffffffffu, s, o);
        if (lane == 0) out[b * 128 + row] = s + linb[row];
    }
}

// ---------------------------------------------------------------------------
extern "C" void kernel_launch(void* const* d_in, const int* in_sizes, int n_in,
                              void* d_out, int out_size)
{
    const float* emb   = (const float*)d_in[0];
    const float* Wc    = (const float*)d_in[1];
    const float* bc    = (const float*)d_in[2];
    const float* Wb    = (const float*)d_in[3];
    const float* Wih_f = (const float*)d_in[4];
    const float* Whh_f = (const float*)d_in[5];
    const float* bih_f = (const float*)d_in[6];
    const float* bhh_f = (const float*)d_in[7];
    const float* Wih_b = (const float*)d_in[8];
    const float* Whh_b = (const float*)d_in[9];
    const float* bih_b = (const float*)d_in[10];
    const float* bhh_b = (const float*)d_in[11];
    const float* linW  = (const float*)d_in[12];
    const float* linb  = (const float*)d_in[13];
    const int* node_tokens = (const int*)d_in[14];
    const int* doc_tokens  = (const int*)d_in[15];
    float* out = (float*)d_out;

    cudaFuncSetAttribute(k1_stmt, cudaFuncAttributeMaxDynamicSharedMemorySize, K1_DYN);
    cudaFuncSetAttribute(k1b_gi,  cudaFuncAttributeMaxDynamicSharedMemorySize, K1B_DYN);
    cudaFuncSetAttribute(k2_gru,  cudaFuncAttributeMaxDynamicSharedMemorySize, K2_DYN);

    k1_stmt<<<148, 512, K1_DYN>>>(emb, Wc, bc, node_tokens);
    k1b_gi<<<144, 512, K1B_DYN>>>(Wih_f, Wih_b, bih_f, bih_b);
    k2_gru<<<144, 384, K2_DYN>>>(Whh_f, bhh_f, Whh_b, bhh_b, emb, Wb, doc_tokens, out);
    k3_out<<<BB, 256>>>(linW, linb, out);
}

// round 16
// speedup vs baseline: 1.1958x; 1.1958x over previous
#include <cuda_runtime.h>
#include <cuda_fp16.h>
#include <math.h>
#include <stdint.h>

#define TS 8192
#define BB 64
#define LL 128
#define DLN 20
#define TP 272      // fp16 tile pitch in BYTES (136 halves)
#define SP 132      // fp32 stage pitch in floats

typedef unsigned long long ull;

// ---------------- scratch (device globals; no allocation allowed) ----------
__device__ float g_gi[TS * 768];                     // 25 MB
__device__ float g_pooled[BB * 256];
__device__ __align__(16) __half g_Af[TS * 128];      // stmt_h, fp16

// subtree sizes of the 32-node binary heap
__constant__ float c_cszf[32] = {32,16,15,8,7,7,7,4,3,3,3,3,3,3,3,2,
                                 1,1,1,1,1,1,1,1,1,1,1,1,1,1,1,1};

// ---------------- helpers ---------------------------------------------------
__device__ __forceinline__ uint32_t s2u(const void* p){
    uint32_t a;
    asm("{ .reg .u64 t; cvta.to.shared.u64 t, %1; cvt.u32.u64 %0, t; }" : "=r"(a) : "l"(p));
    return a;
}
__device__ __forceinline__ void ldsm4(uint32_t addr, uint32_t r[4]){
    asm volatile("ldmatrix.sync.aligned.m8n8.x4.shared.b16 {%0,%1,%2,%3}, [%4];"
        : "=r"(r[0]), "=r"(r[1]), "=r"(r[2]), "=r"(r[3]) : "r"(addr));
}
__device__ __forceinline__ void mma_f16(float d[4], const uint32_t a[4], uint32_t b0, uint32_t b1){
    asm volatile("mma.sync.aligned.m16n8k16.row.col.f32.f16.f16.f32 "
        "{%0,%1,%2,%3}, {%4,%5,%6,%7}, {%8,%9}, {%0,%1,%2,%3};"
        : "+f"(d[0]), "+f"(d[1]), "+f"(d[2]), "+f"(d[3])
        : "r"(a[0]), "r"(a[1]), "r"(a[2]), "r"(a[3]), "r"(b0), "r"(b1));
}
__device__ __forceinline__ float4 f4add(float4 a, float4 b){
    return make_float4(a.x + b.x, a.y + b.y, a.z + b.z, a.w + b.w);
}
__device__ __forceinline__ void cpa16(uint32_t dst, const void* src){
    asm volatile("cp.async.cg.shared.global [%0], [%1], 16;"
        :: "r"(dst), "l"(__cvta_generic_to_global(src)) : "memory");
}
#define CP_COMMIT() asm volatile("cp.async.commit_group;" ::: "memory")
#define CP_WAIT0()  asm volatile("cp.async.wait_group 0;" ::: "memory")

// smem layouts (byte offsets from aligned base). One 128x136 fp16 tile = 34816 B.
// K1:  A | B | stage
#define K1_OFF_A   0
#define K1_OFF_B   34816
#define K1_OFF_STG 69632                 // float[128][132] = 67584 B
#define K1_DYN  (1024 + 69632 + 67584)
// K1b: B | A0 | A1
#define K1B_OFF_B  0
#define K1B_OFF_A0 34816
#define K1B_OFF_A1 69632
#define K1B_DYN (1024 + 104448)
// K3: Wb staged in dynamic smem (rvec CTAs)
#define K3_DYN (128 * 128 * 4)

// 128x64x128 fp16 1-term GEMM slice: warp (wr, wc) does rows 16*wr..+15,
// cols 64*wc..+63 (8 n-tiles).
__device__ __forceinline__ void gemm_tile8_1t(
    uint32_t sA, uint32_t sB,
    int wr, int wc, int lane, float acc[8][4])
{
    const uint32_t aOff = (uint32_t)(((lane & 15) + 16 * wr) * TP + ((lane >> 4) << 4));
    const uint32_t bOff = (uint32_t)((64 * wc + ((lane >> 4) << 3) + (lane & 7)) * TP
                                     + (((lane >> 3) & 1) << 4));
    #pragma unroll
    for (int ks = 0; ks < 8; ks++) {
        const uint32_t ko = ks * 32;          // 16 halves = 32 B
        uint32_t a[4];
        ldsm4(sA + aOff + ko, a);
        uint32_t bP = sB + bOff + ko;
        #pragma unroll
        for (int p = 0; p < 4; p++) {
            uint32_t bh[4];
            ldsm4(bP, bh);
            mma_f16(acc[2 * p],     a, bh[0], bh[1]);
            mma_f16(acc[2 * p + 1], a, bh[2], bh[3]);
            bP += 16 * TP;
        }
    }
}

// convert a 128x128 fp32 weight block (row-major, gmem) into fp16 smem tile
__device__ __forceinline__ void conv_w_tile(char* dst, const float* __restrict__ src, int t){
    #pragma unroll
    for (int i = 0; i < 8; i++) {
        int idx = i * 512 + t;
        int j = idx >> 5, c4 = idx & 31;
        float4 v = *(const float4*)(src + j * 128 + c4 * 4);
        __half2 h0, h1;
        h0.x = __float2half_rn(v.x); h0.y = __float2half_rn(v.y);
        h1.x = __float2half_rn(v.z); h1.y = __float2half_rn(v.w);
        *(__half2*)(dst + j * TP + c4 * 8)     = h0;
        *(__half2*)(dst + j * TP + c4 * 8 + 4) = h1;
    }
}

// issue cp.async gather of 128 embedding rows (512B each) into stage
__device__ __forceinline__ void gather_pref(
    uint32_t stg_u, const float* __restrict__ emb, const int* tk_s, int t)
{
    #pragma unroll
    for (int i = 0; i < 8; i++) {
        int idx = i * 512 + t;
        int row = idx >> 5, ch = idx & 31;
        cpa16(stg_u + (uint32_t)(row * (SP * 4) + ch * 16),
              emb + (size_t)tk_s[row] * 128 + ch * 4);
    }
    CP_COMMIT();
}

// ---------------------------------------------------------------------------
// K1: persistent (grid 148, 512 thr). Per tile (4 statements): prefetched
//     gather -> tree reduce (2 barriers) -> fp16 round -> 1-term mma.sync
//     GEMM vs Wc -> shuffle epilogue -> fp16 staging.
// ---------------------------------------------------------------------------
__global__ __launch_bounds__(512) void k1_stmt(
    const float* __restrict__ emb, const float* __restrict__ Wc,
    const float* __restrict__ bc, const int* __restrict__ toks_g)
{
    extern __shared__ char smraw[];
    __shared__ int tkA[128], tkB[128];
    __shared__ float bcs[128];
    __shared__ float epi[1024];

    const int t = threadIdx.x, w = t >> 5, lane = t & 31;
    const int wr = w & 7, wc = w >> 3;
    const uint32_t rawu = s2u(smraw);
    const uint32_t alu = (rawu + 1023u) & ~1023u;
    char* base = smraw + (alu - rawu);
    float* stg = (float*)(base + K1_OFF_STG);
    float4* As4 = (float4*)stg;
    const uint32_t stg_u = alu + K1_OFF_STG;

    if (t < 128) { bcs[t] = bc[t]; tkA[t] = toks_g[blockIdx.x * 128 + t] + 1; }
    __syncthreads();
    gather_pref(stg_u, emb, tkA, t);
    if ((int)blockIdx.x + 148 < 2048 && t < 128)
        tkB[t] = toks_g[(blockIdx.x + 148) * 128 + t] + 1;

    // Wc fp16 tile once (converted in-CTA from gmem)
    conv_w_tile(base + K1_OFF_B, Wc, t);

    int jpar = 0;
    for (int tile = blockIdx.x; tile < 2048; tile += 148, jpar ^= 1) {
        CP_WAIT0();
        __syncthreads();

        // ---- tree reduce. Pass A: L4 fused into p=7 task + L3 (p=7..14) ----
        #pragma unroll
        for (int i = 0; i < 2; i++) {
            int idx = i * 512 + t;
            int k4 = idx & 31, q = idx >> 5, tt = q & 3, p = 7 + (q >> 2);
            int rb = tt * 32;
            if (p == 7) {
                float4 a15 = f4add(As4[(rb + 15) * 33 + k4], As4[(rb + 31) * 33 + k4]);
                As4[(rb + 15) * 33 + k4] = a15;
                As4[(rb + 7) * 33 + k4] = f4add(As4[(rb + 7) * 33 + k4],
                                          f4add(a15, As4[(rb + 16) * 33 + k4]));
            } else {
                As4[(rb + p) * 33 + k4] = f4add(As4[(rb + p) * 33 + k4],
                    f4add(As4[(rb + 2 * p + 1) * 33 + k4], As4[(rb + 2 * p + 2) * 33 + k4]));
            }
        }
        __syncthreads();
        // ---- Pass B: L2+L1+L0 fused per (stmt, k4) column, register chain ----
        if (t < 128) {
            int tt = t >> 5, k4 = t & 31;
            int rb = tt * 32;
            #define AV(p) As4[(rb + (p)) * 33 + k4]
            float4 a3 = f4add(AV(3), f4add(AV(7),  AV(8)));  AV(3) = a3;
            float4 a4 = f4add(AV(4), f4add(AV(9),  AV(10))); AV(4) = a4;
            float4 a5 = f4add(AV(5), f4add(AV(11), AV(12))); AV(5) = a5;
            float4 a6 = f4add(AV(6), f4add(AV(13), AV(14))); AV(6) = a6;
            float4 a1 = f4add(AV(1), f4add(a3, a4)); AV(1) = a1;
            float4 a2 = f4add(AV(2), f4add(a5, a6)); AV(2) = a2;
            AV(0) = f4add(AV(0), f4add(a1, a2));
            #undef AV
        }
        __syncthreads();

        // ---- fp32 -> fp16 A tile (single rounding) ----
        #pragma unroll
        for (int i = 0; i < 16; i++) {
            int idx = i * 512 + t;
            int row = idx >> 6, c2 = idx & 63;
            float2 v = *(const float2*)(stg + row * SP + c2 * 2);
            __half2 hh;
            hh.x = __float2half_rn(v.x);
            hh.y = __float2half_rn(v.y);
            *(__half2*)(base + K1_OFF_A + row * TP + c2 * 4) = hh;
        }
        __syncthreads();

        // ---- prefetch next tile's gather into (now free) stage ----
        int nxt = tile + 148;
        if (nxt < 2048) gather_pref(stg_u, emb, jpar ? tkA : tkB, t);
        if (nxt + 148 < 2048 && t < 128)
            (jpar ? tkB : tkA)[t] = toks_g[(nxt + 148) * 128 + t] + 1;

        // ---- GEMM (16 warps: wr x wc), 1-term fp16 ----
        float acc[8][4];
        #pragma unroll
        for (int n = 0; n < 8; n++)
            #pragma unroll
            for (int c = 0; c < 4; c++) acc[n][c] = 0.f;
        gemm_tile8_1t(alu + K1_OFF_A, alu + K1_OFF_B, wr, wc, lane, acc);

        // ---- shuffle epilogue: max over 32 nodes of acc + csz*bc, relu ----
        const int rr0 = (wr & 1) * 16 + (lane >> 2);
        const float cz0 = c_cszf[rr0], cz1 = c_cszf[rr0 + 8];
        #pragma unroll
        for (int nt = 0; nt < 8; nt++) {
            int c0 = 64 * wc + nt * 8 + 2 * (lane & 3);
            float b0 = bcs[c0], b1 = bcs[c0 + 1];
            float m0 = fmaxf(acc[nt][0] + cz0 * b0, acc[nt][2] + cz1 * b0);
            float m1 = fmaxf(acc[nt][1] + cz0 * b1, acc[nt][3] + cz1 * b1);
            #pragma unroll
            for (int o = 4; o <= 16; o <<= 1) {
                m0 = fmaxf(m0, __shfl_xor_sync(0xffffffffu, m0, o));
                m1 = fmaxf(m1, __shfl_xor_sync(0xffffffffu, m1, o));
            }
            if ((lane >> 2) == 0) { epi[wr * 128 + c0] = m0; epi[wr * 128 + c0 + 1] = m1; }
        }
        __syncthreads();
        {
            int st = t >> 7, col = t & 127;
            float m = fmaxf(fmaxf(epi[(2 * st) * 128 + col], epi[(2 * st + 1) * 128 + col]), 0.f);
            g_Af[(tile * 4 + st) * 128 + col] = __float2half_rn(m);
        }
        __syncthreads();
    }
}

// ---------------------------------------------------------------------------
// K1b: persistent gi GEMM (512 thr). 144 CTAs = (24 rb-groups x 6 gate-blocks).
//      B converted once from gmem; fp16 A double-buffered via cp.async.
//      Adds bih bias (pre-folded out of k2).
// ---------------------------------------------------------------------------
__device__ __forceinline__ void k1b_prefA(uint32_t dstA, int rb, int t){
    const float4* sa = (const float4*)(g_Af + rb * 16384);
    #pragma unroll
    for (int i = 0; i < 4; i++) {
        int idx = i * 512 + t, jj = idx >> 4, sg = idx & 15;
        cpa16(dstA + jj * TP + sg * 16, sa + idx);
    }
    CP_COMMIT();
}

__global__ __launch_bounds__(512) void k1b_gi(
    const float* __restrict__ Wih_f, const float* __restrict__ Wih_b,
    const float* __restrict__ bih_f, const float* __restrict__ bih_b)
{
    extern __shared__ char smraw[];
    __shared__ float bias_s[128];
    const int t = threadIdx.x, w = t >> 5, lane = t & 31;
    const int wr = w & 7, wc = w >> 3;
    const int by = blockIdx.x % 6, rb0 = blockIdx.x / 6;
    const uint32_t rawu = s2u(smraw);
    const uint32_t alu = (rawu + 1023u) & ~1023u;
    char* base = smraw + (alu - rawu);

    if (t < 128) bias_s[t] = (by < 3) ? bih_f[by * 128 + t] : bih_b[(by - 3) * 128 + t];

    k1b_prefA(alu + K1B_OFF_A0, rb0, t);

    // B gate-block once (converted in-CTA from gmem)
    {
        const float* Wsel = (by < 3) ? (Wih_f + (size_t)by * 128 * 128)
                                     : (Wih_b + (size_t)(by - 3) * 128 * 128);
        conv_w_tile(base + K1B_OFF_B, Wsel, t);
    }

    int pb = 0;
    for (int rb = rb0; rb < 64; rb += 24, pb ^= 1) {
        CP_WAIT0();
        __syncthreads();
        if (rb + 24 < 64)
            k1b_prefA(alu + (pb ? K1B_OFF_A0 : K1B_OFF_A1), rb + 24, t);

        float acc[8][4];
        #pragma unroll
        for (int n = 0; n < 8; n++)
            #pragma unroll
            for (int c = 0; c < 4; c++) acc[n][c] = 0.f;
        gemm_tile8_1t(alu + (pb ? K1B_OFF_A1 : K1B_OFF_A0),
                      alu + K1B_OFF_B, wr, wc, lane, acc);

        const int row = rb * 128 + 16 * wr + (lane >> 2);
        float* o0 = g_gi + (size_t)row * 768 + by * 128 + 64 * wc;
        float* o1 = o0 + 8 * 768;
        const int cb = (lane & 3) * 2;
        #pragma unroll
        for (int nt = 0; nt < 8; nt++) {
            float b0 = bias_s[64 * wc + nt * 8 + cb];
            float b1 = bias_s[64 * wc + nt * 8 + cb + 1];
            *(float2*)(o0 + nt * 8 + cb) = make_float2(acc[nt][0] + b0, acc[nt][1] + b1);
            *(float2*)(o1 + nt * 8 + cb) = make_float2(acc[nt][2] + b0, acc[nt][3] + b1);
        }
    }
}

// ---------------------------------------------------------------------------
__device__ __forceinline__ void ffma2(ull& d, ull a, ull b){
    asm("fma.rn.f32x2 %0, %1, %2, %0;" : "+l"(d) : "l"(a), "l"(b));
}
__device__ __forceinline__ float2 ull2f2(ull v){
    float2 f; asm("mov.b64 {%0, %1}, %2;" : "=f"(f.x), "=f"(f.y) : "l"(v)); return f;
}

// ---------------------------------------------------------------------------
// K2: GRU recurrence (pure, as measured in R14). 128 CTAs. 384 threads:
//     thread (g, tt) owns rows 2tt, 2tt+1 for h-half g. gi via direct LDG.
//     bhh held in gate-thread registers.
// ---------------------------------------------------------------------------
__global__ __launch_bounds__(384) void k2_gru(
    const float* __restrict__ Whh_f, const float* __restrict__ bhh_f,
    const float* __restrict__ Whh_b, const float* __restrict__ bhh_b)
{
    __shared__ float h_s[128];
    __shared__ float part[768];              // [half][row]

    const int t = threadIdx.x;
    const int b = blockIdx.x >> 1, dir = blockIdx.x & 1;
    const float* Whh = dir ? Whh_b : Whh_f;
    const float* bhh = dir ? bhh_b : bhh_f;

    const int g  = (t < 192) ? 0 : 1;
    const int tt = (t < 192) ? t : t - 192;
    const int j0 = 2 * tt;                   // rows j0, j0+1

    ull w0[32], w1[32];                      // 2 rows x 64 cols fp32
    {
        const ulonglong2* p0 = (const ulonglong2*)(Whh + (size_t)j0 * 128 + g * 64);
        const ulonglong2* p1 = (const ulonglong2*)(Whh + (size_t)(j0 + 1) * 128 + g * 64);
        #pragma unroll
        for (int i = 0; i < 16; i++) {
            ulonglong2 v0 = p0[i]; w0[2*i] = v0.x; w0[2*i+1] = v0.y;
            ulonglong2 v1 = p1[i]; w1[2*i] = v1.x; w1[2*i+1] = v1.y;
        }
    }
    float bhr = 0.f, bhz = 0.f, bhn = 0.f;
    if (t < 128) {
        bhr = bhh[t]; bhz = bhh[128 + t]; bhn = bhh[256 + t];
        h_s[t] = 0.f;
    }

    const float* gbase = g_gi + (size_t)(b * LL + (dir ? LL - 1 : 0)) * 768 + dir * 384;
    const int stp = dir ? -768 : 768;
    __syncthreads();

    float hmax = -3e38f;
    for (int l = 0; l < LL; l++) {
        float gr, gz, gn;
        if (t < 128) {
            const float* gp = gbase + (ptrdiff_t)l * stp;
            gr = __ldg(gp + t);
            gz = __ldg(gp + 128 + t);
            gn = __ldg(gp + 256 + t);
        }

        ull a00 = 0, a01 = 0, a10 = 0, a11 = 0;
        const ulonglong2* hp = (const ulonglong2*)(h_s + g * 64);
        #pragma unroll
        for (int i = 0; i < 16; i++) {
            ulonglong2 hv = hp[i];
            ffma2(a00, w0[2*i],     hv.x);
            ffma2(a01, w0[2*i + 1], hv.y);
            ffma2(a10, w1[2*i],     hv.x);
            ffma2(a11, w1[2*i + 1], hv.y);
        }
        float2 f00 = ull2f2(a00), f01 = ull2f2(a01);
        float2 f10 = ull2f2(a10), f11 = ull2f2(a11);
        *(float2*)(part + g * 384 + j0) = make_float2(
            (f00.x + f00.y) + (f01.x + f01.y),
            (f10.x + f10.y) + (f11.x + f11.y));
        __syncthreads();

        if (t < 128) {
            float ghr = part[t]       + part[384 + t] + bhr;
            float ghz = part[128 + t] + part[512 + t] + bhz;
            float ghn = part[256 + t] + part[640 + t] + bhn;
            float r = __fdividef(1.f, 1.f + __expf(-(gr + ghr)));
            float z = __fdividef(1.f, 1.f + __expf(-(gz + ghz)));
            float y = gn + r * ghn;
            float n = 1.f - __fdividef(2.f, __expf(2.f * y) + 1.f);
            float hnew = (1.f - z) * n + z * h_s[t];
            h_s[t] = hnew;
            hmax = fmaxf(hmax, hnew);
        }
        __syncthreads();
    }
    if (t < 128) g_pooled[b * 256 + dir * 128 + t] = hmax;
}

// ---------------------------------------------------------------------------
// K3: grid 128 = (batch, half), 512 thr. half 1: lvec. half 0: doc attention
//     (Wb + demb staged in one memory phase, warp-parallel softmax).
// ---------------------------------------------------------------------------
__global__ __launch_bounds__(512) void k3_out(
    const float* __restrict__ emb, const float* __restrict__ Wb,
    const float* __restrict__ linW, const float* __restrict__ linb,
    const int* __restrict__ doc, float* __restrict__ out)
{
    extern __shared__ float Wbs[];           // 128*128 floats (rvec CTAs)
    __shared__ float demb[DLN * 128];
    __shared__ float h0[128];
    __shared__ float u[128];
    __shared__ float exs[32];
    __shared__ float inv_s;
    __shared__ float pool[256];
    __shared__ int dti[DLN];

    const int t = threadIdx.x, wid = t >> 5, lane = t & 31;
    const int b = blockIdx.x >> 1, half = blockIdx.x & 1;

    if (half) {
        // ---- lvec: pooled @ linW^T + linb (16 warps x 8 rows) ----
        if (t < 256) pool[t] = g_pooled[b * 256 + t];
        __syncthreads();
        #pragma unroll
        for (int rr = 0; rr < 8; rr++) {
            int row = wid * 8 + rr;
            const float* wr = linW + row * 256;
            float s = 0.f;
            #pragma unroll
            for (int q = 0; q < 8; q++) s += wr[lane + 32 * q] * pool[lane + 32 * q];
            #pragma unroll
            for (int o = 16; o > 0; o >>= 1) s += __shfl_xor_sync(0xffffffffu, s, o);
            if (lane == 0) out[b * 128 + row] = s + linb[row];
        }
        return;
    }

    // ---- rvec: doc attention ----
    if (t < DLN) dti[t] = doc[b * DLN + t] + 1;
    __syncthreads();
    // one combined memory phase: Wb (64 KB) + demb (10 KB)
    #pragma unroll
    for (int i = 0; i < 8; i++) {
        int idx = i * 512 + t;
        *(float4*)(Wbs + idx * 4) = *(const float4*)(Wb + idx * 4);
    }
    #pragma unroll
    for (int i = 0; i < 2; i++) {
        int idx = i * 512 + t;
        if (idx < DLN * 32) {
            int l = idx >> 5, c4 = idx & 31;
            *(float4*)(demb + l * 128 + c4 * 4) =
                *(const float4*)(emb + (size_t)dti[l] * 128 + c4 * 4);
        }
    }
    __syncthreads();

    if (t < 128) {
        float s = 0.f;
        #pragma unroll
        for (int l = 0; l < DLN; l++) s += demb[l * 128 + t];
        h0[t] = s * (1.f / (float)DLN);
    }
    __syncthreads();

    // u = Wb @ h0 from smem (16 warps x 8 rows)
    #pragma unroll
    for (int rr = 0; rr < 8; rr++) {
        int row = wid * 8 + rr;
        const float* wr = Wbs + row * 128;
        float s = wr[lane] * h0[lane] + wr[lane + 32] * h0[lane + 32]
                + wr[lane + 64] * h0[lane + 64] + wr[lane + 96] * h0[lane + 96];
        #pragma unroll
        for (int o = 16; o > 0; o >>= 1) s += __shfl_xor_sync(0xffffffffu, s, o);
        if (lane == 0) u[row] = s;
    }
    __syncthreads();

    // scores (16 warps cover DLN=20 in 2 rounds)
    for (int l = wid; l < DLN; l += 16) {
        const float* dr = demb + l * 128;
        float s = dr[lane] * u[lane] + dr[lane + 32] * u[lane + 32]
                + dr[lane + 64] * u[lane + 64] + dr[lane + 96] * u[lane + 96];
        #pragma unroll
        for (int o = 16; o > 0; o >>= 1) s += __shfl_xor_sync(0xffffffffu, s, o);
        if (lane == 0) exs[l] = s;
    }
    __syncthreads();

    // warp-parallel softmax (warp 0)
    if (wid == 0) {
        float v = (lane < DLN) ? exs[lane] : -3e38f;
        float m = v;
        #pragma unroll
        for (int o = 16; o > 0; o >>= 1) m = fmaxf(m, __shfl_xor_sync(0xffffffffu, m, o));
        float e = (lane < DLN) ? expf(v - m) : 0.f;
        float ssum = e;
        #pragma unroll
        for (int o = 16; o > 0; o >>= 1) ssum += __shfl_xor_sync(0xffffffffu, ssum, o);
        if (lane < DLN) exs[lane] = e;
        if (lane == 0) inv_s = 1.f / ssum;
    }
    __syncthreads();

    if (t < 128) {
        float rv = 0.f;
        #pragma unroll
        for (int l = 0; l < DLN; l++) rv += exs[l] * demb[l * 128 + t];
        out[BB * 128 + b * 128 + t] = rv * inv_s;
    }
}

// ---------------------------------------------------------------------------
extern "C" void kernel_launch(void* const* d_in, const int* in_sizes, int n_in,
                              void* d_out, int out_size)
{
    const float* emb   = (const float*)d_in[0];
    const float* Wc    = (const float*)d_in[1];
    const float* bc    = (const float*)d_in[2];
    const float* Wb    = (const float*)d_in[3];
    const float* Wih_f = (const float*)d_in[4];
    const float* Whh_f = (const float*)d_in[5];
    const float* bih_f = (const float*)d_in[6];
    const float* bhh_f = (const float*)d_in[7];
    const float* Wih_b = (const float*)d_in[8];
    const float* Whh_b = (const float*)d_in[9];
    const float* bih_b = (const float*)d_in[10];
    const float* bhh_b = (const float*)d_in[11];
    const float* linW  = (const float*)d_in[12];
    const float* linb  = (const float*)d_in[13];
    const int* node_tokens = (const int*)d_in[14];
    const int* doc_tokens  = (const int*)d_in[15];
    float* out = (float*)d_out;

    cudaFuncSetAttribute(k1_stmt, cudaFuncAttributeMaxDynamicSharedMemorySize, K1_DYN);
    cudaFuncSetAttribute(k1b_gi,  cudaFuncAttributeMaxDynamicSharedMemorySize, K1B_DYN);
    cudaFuncSetAttribute(k3_out,  cudaFuncAttributeMaxDynamicSharedMemorySize, K3_DYN);

    k1_stmt<<<148, 512, K1_DYN>>>(emb, Wc, bc, node_tokens);
    k1b_gi<<<144, 512, K1B_DYN>>>(Wih_f, Wih_b, bih_f, bih_b);
    k2_gru<<<BB * 2, 384>>>(Whh_f, bhh_f, Whh_b, bhh_b);
    k3_out<<<BB * 2, 512, K3_DYN>>>(emb, Wb, linW, linb, doc_tokens, out);
}